// round 1
// baseline (speedup 1.0000x reference)
#include <cuda_runtime.h>
#include <math.h>

#define DMODEL 1024
#define SEQ 512
#define BATCH 64
#define NTOK (BATCH * SEQ)

// ---------------- scratch (static device globals; no allocation) ----------------
__device__ float g_emb[(size_t)NTOK * DMODEL];
__device__ float g_h1[(size_t)NTOK * DMODEL];
__device__ float g_h2[(size_t)NTOK * DMODEL];
__device__ float g_q[(size_t)NTOK * DMODEL];
__device__ float g_k[(size_t)NTOK * DMODEL];
__device__ float g_v[(size_t)NTOK * DMODEL];
__device__ float g_attn[(size_t)NTOK * DMODEL];
__device__ float g_pooled[BATCH * DMODEL];
__device__ int g_is64;

// ---------------- dtype detection: int64 vs int32 token ids ----------------
// Safe to read 32768 int32 words in both cases (int32: exactly the buffer;
// int64: first half of buffer). If dtype is int64, every odd word is the high
// half of a small nonnegative value => 0. With int32 data the odd words are
// random tokens; all-zero is impossible in practice.
__global__ void detect_kernel(const int* __restrict__ x) {
    __shared__ int any;
    if (threadIdx.x == 0) any = 0;
    __syncthreads();
    int local = 0;
    for (int i = threadIdx.x * 2 + 1; i < NTOK; i += blockDim.x * 2) local |= x[i];
    if (local) atomicOr(&any, 1);
    __syncthreads();
    if (threadIdx.x == 0) g_is64 = (any == 0) ? 1 : 0;
}

__device__ __forceinline__ long long get_id(const void* x, int i) {
    return g_is64 ? ((const long long*)x)[i] : (long long)((const int*)x)[i];
}

// ---------------- embedding: g_emb = emb_w[x] + pos_w[s] ----------------
__global__ void embed_kernel(const void* __restrict__ x,
                             const float* __restrict__ emb_w,
                             const float* __restrict__ pos_w) {
    int tok = blockIdx.x;               // 0..NTOK-1
    int s = tok & (SEQ - 1);
    long long id = get_id(x, tok);
    const float4* ew = (const float4*)(emb_w + (size_t)id * DMODEL);
    const float4* pw = (const float4*)(pos_w + (size_t)s * DMODEL);
    float4* out = (float4*)(g_emb + (size_t)tok * DMODEL);
    for (int i = threadIdx.x; i < DMODEL / 4; i += blockDim.x) {
        float4 a = ew[i], b = pw[i];
        out[i] = make_float4(a.x + b.x, a.y + b.y, a.z + b.z, a.w + b.w);
    }
}

// ---------------- sgemm: C[M,1024] = A[M,1024] @ W[1024,1024] + bias (+ res) ----------------
// 128x128 block tile, BK=8, 256 threads, 8x8 per thread, register prefetch.
__global__ __launch_bounds__(256) void sgemm_kernel(
    const float* __restrict__ A, const float* __restrict__ W,
    const float* __restrict__ bias, const float* __restrict__ res,
    float* __restrict__ C) {
    const int K = DMODEL, N = DMODEL;
    __shared__ float As[8][128];
    __shared__ float Bs[8][128];
    int bm = blockIdx.y, bn = blockIdx.x;
    int tid = threadIdx.x;
    int arow = tid >> 1, acol = (tid & 1) * 4;
    int brow = tid >> 5, bcol = (tid & 31) * 4;
    int warp = tid >> 5, lane = tid & 31;
    int wm = (warp >> 2) * 64;   // 2 warps along M
    int wn = (warp & 3) * 32;    // 4 warps along N
    int tm = wm + (lane >> 2) * 8;
    int tn = wn + (lane & 3) * 8;

    float acc[8][8];
#pragma unroll
    for (int i = 0; i < 8; i++)
#pragma unroll
        for (int j = 0; j < 8; j++) acc[i][j] = 0.f;

    const float* Aptr = A + (size_t)(bm * 128 + arow) * K + acol;
    const float* Bptr = W + (size_t)brow * N + bn * 128 + bcol;

    float4 areg = *(const float4*)(Aptr);
    float4 breg = *(const float4*)(Bptr);

    for (int k0 = 0; k0 < K; k0 += 8) {
        As[acol + 0][arow] = areg.x;
        As[acol + 1][arow] = areg.y;
        As[acol + 2][arow] = areg.z;
        As[acol + 3][arow] = areg.w;
        *(float4*)&Bs[brow][bcol] = breg;
        __syncthreads();
        if (k0 + 8 < K) {
            areg = *(const float4*)(Aptr + k0 + 8);
            breg = *(const float4*)(Bptr + (size_t)(k0 + 8) * N);
        }
#pragma unroll
        for (int kk = 0; kk < 8; kk++) {
            float ar[8], br[8];
            *(float4*)(ar)     = *(float4*)&As[kk][tm];
            *(float4*)(ar + 4) = *(float4*)&As[kk][tm + 4];
            *(float4*)(br)     = *(float4*)&Bs[kk][tn];
            *(float4*)(br + 4) = *(float4*)&Bs[kk][tn + 4];
#pragma unroll
            for (int i = 0; i < 8; i++)
#pragma unroll
                for (int j = 0; j < 8; j++) acc[i][j] += ar[i] * br[j];
        }
        __syncthreads();
    }

#pragma unroll
    for (int i = 0; i < 8; i++) {
        size_t row = (size_t)(bm * 128 + tm + i);
        float* crow = C + row * N + bn * 128;
        const float* rrow = res + row * N + bn * 128;  // valid only if res != null
#pragma unroll
        for (int j = 0; j < 8; j += 4) {
            int col = tn + j;
            float4 o;
            o.x = acc[i][j + 0] + bias[bn * 128 + col + 0];
            o.y = acc[i][j + 1] + bias[bn * 128 + col + 1];
            o.z = acc[i][j + 2] + bias[bn * 128 + col + 2];
            o.w = acc[i][j + 3] + bias[bn * 128 + col + 3];
            if (res) {
                float4 r = *(const float4*)(rrow + col);
                o.x += r.x; o.y += r.y; o.z += r.z; o.w += r.w;
            }
            *(float4*)(crow + col) = o;
        }
    }
}

// ---------------- flash attention, key-padding mask ----------------
// Block: (q-tile of 64, head h, batch b), 256 threads.
// Dynamic smem: Qs[64][DH+4], Ks[64][DH+4], Vs[64][DH+4], Ss[64][65].
template <int DH>
__global__ __launch_bounds__(256) void attn_kernel(
    const float* __restrict__ Q, const float* __restrict__ Kt,
    const float* __restrict__ Vt, const void* __restrict__ xids,
    float* __restrict__ O, int H) {
    extern __shared__ float sm[];
    const int STR = DH + 4;
    const int CH = DH / 4;   // per-thread accumulator chunk
    float* Qs = sm;
    float* Ks = Qs + 64 * STR;
    float* Vs = Ks + 64 * STR;
    float* Ss = Vs + 64 * STR;   // [64][65]
    __shared__ int msk[64];

    int qt = blockIdx.x, h = blockIdx.y, b = blockIdx.z;
    int tid = threadIdx.x;
    float scale = rsqrtf((float)DH);
    int q0 = qt * 64;
    const int vecs = 64 * (DH / 4);

    // load Q tile
    for (int i = tid; i < vecs; i += 256) {
        int r = i / (DH / 4), c = i % (DH / 4);
        float4 v = *(const float4*)(Q + ((size_t)(b * SEQ + q0 + r) * DMODEL + h * DH + c * 4));
        *(float4*)&Qs[r * STR + c * 4] = v;
    }

    int qr = tid & 63;     // owned query row (accumulation)
    int cc = tid >> 6;     // owned d-chunk 0..3
    float acc[CH];
#pragma unroll
    for (int i = 0; i < CH; i++) acc[i] = 0.f;
    float m_i = -1e30f, l_i = 0.f;

    int sq = tid >> 2;          // score phase: query row
    int skc = tid & 3;          // score phase: key lane (keys skc + 4j, conflict-free)
    int is64 = g_is64;

    for (int kt = 0; kt < SEQ / 64; kt++) {
        int k0 = kt * 64;
        __syncthreads();   // protect Ks/Vs/Ss from previous iteration consumers
        for (int i = tid; i < vecs; i += 256) {
            int r = i / (DH / 4), c = i % (DH / 4);
            size_t base = ((size_t)(b * SEQ + k0 + r) * DMODEL + h * DH + c * 4);
            *(float4*)&Ks[r * STR + c * 4] = *(const float4*)(Kt + base);
            *(float4*)&Vs[r * STR + c * 4] = *(const float4*)(Vt + base);
        }
        if (tid < 64) {
            long long idv = is64 ? ((const long long*)xids)[b * SEQ + k0 + tid]
                                 : (long long)((const int*)xids)[b * SEQ + k0 + tid];
            msk[tid] = (idv != 0) ? 1 : 0;
        }
        __syncthreads();

        // scores: 16 keys per thread for row sq
        {
            float dots[16];
#pragma unroll
            for (int j = 0; j < 16; j++) dots[j] = 0.f;
            for (int x = 0; x < DH; x += 4) {
                float4 qv = *(float4*)&Qs[sq * STR + x];
#pragma unroll
                for (int j = 0; j < 16; j++) {
                    float4 kv = *(float4*)&Ks[(skc + 4 * j) * STR + x];
                    dots[j] += qv.x * kv.x + qv.y * kv.y + qv.z * kv.z + qv.w * kv.w;
                }
            }
#pragma unroll
            for (int j = 0; j < 16; j++) {
                int kk = skc + 4 * j;
                Ss[sq * 65 + kk] = msk[kk] ? dots[j] * scale : -1e30f;
            }
        }
        __syncthreads();

        // online softmax + P@V for owned (qr, chunk cc)
        float rowmax = -1e30f;
        for (int kk = 0; kk < 64; kk++) rowmax = fmaxf(rowmax, Ss[qr * 65 + kk]);
        float newm = fmaxf(m_i, rowmax);
        float factor = __expf(m_i - newm);
        l_i *= factor;
#pragma unroll
        for (int i = 0; i < CH; i++) acc[i] *= factor;
        for (int kk = 0; kk < 64; kk++) {
            float s = Ss[qr * 65 + kk];
            float p = (s > -1e29f) ? __expf(s - newm) : 0.f;
            l_i += p;
            const float4* vr = (const float4*)&Vs[kk * STR + cc * CH];
#pragma unroll
            for (int i = 0; i < CH / 4; i++) {
                float4 v = vr[i];
                acc[4 * i + 0] += p * v.x;
                acc[4 * i + 1] += p * v.y;
                acc[4 * i + 2] += p * v.z;
                acc[4 * i + 3] += p * v.w;
            }
        }
        m_i = newm;
    }

    float inv = 1.0f / fmaxf(l_i, 1e-20f);
    size_t base = (size_t)(b * SEQ + q0 + qr) * DMODEL + h * DH + cc * CH;
#pragma unroll
    for (int i = 0; i < CH; i += 4) {
        float4 o = make_float4(acc[i] * inv, acc[i + 1] * inv, acc[i + 2] * inv, acc[i + 3] * inv);
        *(float4*)(O + base + i) = o;
    }
}

// ---------------- masked mean pooling of (g_h2 + g_emb) ----------------
// grid (8, BATCH): block handles 128 columns of one batch row; 128 threads.
__global__ void pool_kernel(const void* __restrict__ xids) {
    int b = blockIdx.y;
    int col = blockIdx.x * 128 + threadIdx.x;
    __shared__ int smask[SEQ];
    int is64 = g_is64;
    for (int s = threadIdx.x; s < SEQ; s += 128) {
        long long idv = is64 ? ((const long long*)xids)[b * SEQ + s]
                             : (long long)((const int*)xids)[b * SEQ + s];
        smask[s] = (idv != 0) ? 1 : 0;
    }
    __syncthreads();
    float acc = 0.f;
    int cnt = 0;
    for (int s = 0; s < SEQ; s++) {
        if (smask[s]) {
            size_t idx = (size_t)(b * SEQ + s) * DMODEL + col;
            acc += g_h2[idx] + g_emb[idx];
            cnt++;
        }
    }
    g_pooled[b * DMODEL + col] = acc / (float)cnt;
}

// ---------------- LayerNorm + linear head ----------------
__global__ void lnlin_kernel(const float* __restrict__ ng, const float* __restrict__ nb,
                             const float* __restrict__ lw, const float* __restrict__ lb,
                             float* __restrict__ out) {
    int b = blockIdx.x, tid = threadIdx.x;   // 256 threads
    __shared__ float red[256];
    float x[4];
    float s = 0.f;
#pragma unroll
    for (int k = 0; k < 4; k++) {
        x[k] = g_pooled[b * DMODEL + tid + k * 256];
        s += x[k];
    }
    red[tid] = s; __syncthreads();
    for (int st = 128; st > 0; st >>= 1) { if (tid < st) red[tid] += red[tid + st]; __syncthreads(); }
    float mu = red[0] / (float)DMODEL;
    __syncthreads();
    float s2 = 0.f;
#pragma unroll
    for (int k = 0; k < 4; k++) { float d = x[k] - mu; s2 += d * d; }
    red[tid] = s2; __syncthreads();
    for (int st = 128; st > 0; st >>= 1) { if (tid < st) red[tid] += red[tid + st]; __syncthreads(); }
    float var = red[0] / (float)DMODEL;
    float rstd = rsqrtf(var + 1e-5f);
    __syncthreads();
    float acc = 0.f;
#pragma unroll
    for (int k = 0; k < 4; k++) {
        int col = tid + k * 256;
        acc += ((x[k] - mu) * rstd * ng[col] + nb[col]) * lw[col];
    }
    red[tid] = acc; __syncthreads();
    for (int st = 128; st > 0; st >>= 1) { if (tid < st) red[tid] += red[tid + st]; __syncthreads(); }
    if (tid == 0) out[b] = red[0] + lb[0];
}

// ---------------- launch ----------------
extern "C" void kernel_launch(void* const* d_in, const int* in_sizes, int n_in,
                              void* d_out, int out_size) {
    const void*  x      = d_in[0];
    const float* emb_w  = (const float*)d_in[1];
    const float* pos_w  = (const float*)d_in[2];
    const float* a1_qw  = (const float*)d_in[3];
    const float* a1_qb  = (const float*)d_in[4];
    const float* a1_kw  = (const float*)d_in[5];
    const float* a1_kb  = (const float*)d_in[6];
    const float* a1_vw  = (const float*)d_in[7];
    const float* a1_vb  = (const float*)d_in[8];
    const float* a1_pw  = (const float*)d_in[9];
    const float* a1_pb  = (const float*)d_in[10];
    const float* a2_qw  = (const float*)d_in[11];
    const float* a2_qb  = (const float*)d_in[12];
    const float* a2_kw  = (const float*)d_in[13];
    const float* a2_kb  = (const float*)d_in[14];
    const float* a2_vw  = (const float*)d_in[15];
    const float* a2_vb  = (const float*)d_in[16];
    const float* a2_pw  = (const float*)d_in[17];
    const float* a2_pb  = (const float*)d_in[18];
    const float* norm_g = (const float*)d_in[19];
    const float* norm_b = (const float*)d_in[20];
    const float* lin_w  = (const float*)d_in[21];
    const float* lin_b  = (const float*)d_in[22];
    float* out = (float*)d_out;

    float *p_emb, *p_h1, *p_h2, *p_q, *p_k, *p_v, *p_attn;
    cudaGetSymbolAddress((void**)&p_emb,  g_emb);
    cudaGetSymbolAddress((void**)&p_h1,   g_h1);
    cudaGetSymbolAddress((void**)&p_h2,   g_h2);
    cudaGetSymbolAddress((void**)&p_q,    g_q);
    cudaGetSymbolAddress((void**)&p_k,    g_k);
    cudaGetSymbolAddress((void**)&p_v,    g_v);
    cudaGetSymbolAddress((void**)&p_attn, g_attn);

    const int smem128 = (3 * 64 * (128 + 4) + 64 * 65) * 4;   // 118016
    const int smem256 = (3 * 64 * (256 + 4) + 64 * 65) * 4;   // 216320
    cudaFuncSetAttribute(attn_kernel<128>, cudaFuncAttributeMaxDynamicSharedMemorySize, smem128);
    cudaFuncSetAttribute(attn_kernel<256>, cudaFuncAttributeMaxDynamicSharedMemorySize, smem256);

    detect_kernel<<<1, 256>>>((const int*)x);
    embed_kernel<<<NTOK, 256>>>(x, emb_w, pos_w);

    dim3 gg(DMODEL / 128, NTOK / 128);   // (8, 256)

    // Layer 1 (8 heads, dh=128)
    sgemm_kernel<<<gg, 256>>>(p_emb, a1_qw, a1_qb, nullptr, p_q);
    sgemm_kernel<<<gg, 256>>>(p_emb, a1_kw, a1_kb, nullptr, p_k);
    sgemm_kernel<<<gg, 256>>>(p_emb, a1_vw, a1_vb, nullptr, p_v);
    attn_kernel<128><<<dim3(SEQ / 64, 8, BATCH), 256, smem128>>>(p_q, p_k, p_v, x, p_attn, 8);
    sgemm_kernel<<<gg, 256>>>(p_attn, a1_pw, a1_pb, p_emb, p_h1);

    // Layer 2 (4 heads, dh=256)
    sgemm_kernel<<<gg, 256>>>(p_h1, a2_qw, a2_qb, nullptr, p_q);
    sgemm_kernel<<<gg, 256>>>(p_h1, a2_kw, a2_kb, nullptr, p_k);
    sgemm_kernel<<<gg, 256>>>(p_h1, a2_vw, a2_vb, nullptr, p_v);
    attn_kernel<256><<<dim3(SEQ / 64, 4, BATCH), 256, smem256>>>(p_q, p_k, p_v, x, p_attn, 4);
    sgemm_kernel<<<gg, 256>>>(p_attn, a2_pw, a2_pb, p_h1, p_h2);

    // Pool + LN + head
    pool_kernel<<<dim3(DMODEL / 128, BATCH), 128>>>(x);
    lnlin_kernel<<<BATCH, 256>>>(norm_g, norm_b, lin_w, lin_b, out);
}

// round 5
// speedup vs baseline: 1.1898x; 1.1898x over previous
#include <cuda_runtime.h>
#include <cuda_bf16.h>
#include <cstdint>
#include <math.h>

#define DMODEL 1024
#define SEQ 512
#define BATCH 64
#define NTOK (BATCH * SEQ)

// ---------------- scratch (static device globals; no allocation) ----------------
__device__ float g_emb[(size_t)NTOK * DMODEL];
__device__ float g_h1[(size_t)NTOK * DMODEL];
__device__ float g_h2[(size_t)NTOK * DMODEL];
__device__ float g_q[(size_t)NTOK * DMODEL];
__device__ float g_k[(size_t)NTOK * DMODEL];
__device__ float g_v[(size_t)NTOK * DMODEL];
__device__ __nv_bfloat16 g_ahi[(size_t)NTOK * DMODEL];   // activation hi (emb -> h1 -> attn reuse)
__device__ __nv_bfloat16 g_alo[(size_t)NTOK * DMODEL];   // activation lo
__device__ __nv_bfloat16 g_bhi[(size_t)NTOK * DMODEL];   // second activation hi buffer
__device__ __nv_bfloat16 g_blo[(size_t)NTOK * DMODEL];   // second activation lo buffer
__device__ __nv_bfloat16 g_whi[(size_t)8 * DMODEL * DMODEL];
__device__ __nv_bfloat16 g_wlo[(size_t)8 * DMODEL * DMODEL];
__device__ float g_pooled[BATCH * DMODEL];
__device__ int g_is64;

// ---------------- helpers ----------------
__device__ __forceinline__ uint32_t smem_u32(const void* p) {
    uint32_t a;
    asm("{ .reg .u64 t; cvta.to.shared.u64 t, %1; cvt.u32.u64 %0, t; }" : "=r"(a) : "l"(p));
    return a;
}
__device__ __forceinline__ void cp_async16(uint32_t dst, const void* src) {
    asm volatile("cp.async.cg.shared.global [%0], [%1], 16;" :: "r"(dst), "l"(src));
}
__device__ __forceinline__ void ldsm_x4(uint32_t& r0, uint32_t& r1, uint32_t& r2, uint32_t& r3,
                                        uint32_t addr) {
    asm volatile("ldmatrix.sync.aligned.m8n8.x4.shared.b16 {%0,%1,%2,%3}, [%4];"
                 : "=r"(r0), "=r"(r1), "=r"(r2), "=r"(r3) : "r"(addr));
}
__device__ __forceinline__ void mma_bf16(float& c0, float& c1, float& c2, float& c3,
                                         uint32_t a0, uint32_t a1, uint32_t a2, uint32_t a3,
                                         uint32_t b0, uint32_t b1) {
    asm volatile("mma.sync.aligned.m16n8k16.row.col.f32.bf16.bf16.f32 "
                 "{%0,%1,%2,%3}, {%4,%5,%6,%7}, {%8,%9}, {%0,%1,%2,%3};"
                 : "+f"(c0), "+f"(c1), "+f"(c2), "+f"(c3)
                 : "r"(a0), "r"(a1), "r"(a2), "r"(a3), "r"(b0), "r"(b1));
}
__device__ __forceinline__ void split_bf16(float v, __nv_bfloat16& hi, __nv_bfloat16& lo) {
    hi = __float2bfloat16_rn(v);
    lo = __float2bfloat16_rn(v - __bfloat162float(hi));
}

// ---------------- dtype detection: int64 vs int32 token ids ----------------
__global__ void detect_kernel(const int* __restrict__ x) {
    __shared__ int any;
    if (threadIdx.x == 0) any = 0;
    __syncthreads();
    int local = 0;
    for (int i = threadIdx.x * 2 + 1; i < NTOK; i += blockDim.x * 2) local |= x[i];
    if (local) atomicOr(&any, 1);
    __syncthreads();
    if (threadIdx.x == 0) g_is64 = (any == 0) ? 1 : 0;
}
__device__ __forceinline__ long long get_id(const void* x, int i) {
    return g_is64 ? ((const long long*)x)[i] : (long long)((const int*)x)[i];
}

// ---------------- weight transpose + bf16 hi/lo: WT[n][k] from W[k][n] ----------------
__global__ void wtrans_kernel(const float* __restrict__ W,
                              __nv_bfloat16* __restrict__ WThi,
                              __nv_bfloat16* __restrict__ WTlo) {
    __shared__ float t[32][33];
    int n0 = blockIdx.x * 32, k0 = blockIdx.y * 32;
    int tx = threadIdx.x, ty = threadIdx.y;
#pragma unroll
    for (int i = 0; i < 4; i++)
        t[ty + 8 * i][tx] = W[(size_t)(k0 + ty + 8 * i) * DMODEL + n0 + tx];
    __syncthreads();
#pragma unroll
    for (int i = 0; i < 4; i++) {
        float v = t[tx][ty + 8 * i];
        __nv_bfloat16 hi, lo;
        split_bf16(v, hi, lo);
        size_t idx = (size_t)(n0 + ty + 8 * i) * DMODEL + k0 + tx;
        WThi[idx] = hi;
        WTlo[idx] = lo;
    }
}

// ---------------- embedding: fp32 + bf16 hi/lo outputs ----------------
__global__ void embed_kernel(const void* __restrict__ x,
                             const float* __restrict__ emb_w,
                             const float* __restrict__ pos_w) {
    int tok = blockIdx.x;
    int s = tok & (SEQ - 1);
    long long id = get_id(x, tok);
    const float4* ew = (const float4*)(emb_w + (size_t)id * DMODEL);
    const float4* pw = (const float4*)(pos_w + (size_t)s * DMODEL);
    float4* out = (float4*)(g_emb + (size_t)tok * DMODEL);
    __nv_bfloat16* ohi = g_ahi + (size_t)tok * DMODEL;
    __nv_bfloat16* olo = g_alo + (size_t)tok * DMODEL;
    for (int i = threadIdx.x; i < DMODEL / 4; i += blockDim.x) {
        float4 a = ew[i], b = pw[i];
        float4 o = make_float4(a.x + b.x, a.y + b.y, a.z + b.z, a.w + b.w);
        out[i] = o;
        __nv_bfloat16 h0, l0, h1, l1, h2, l2, h3, l3;
        split_bf16(o.x, h0, l0); split_bf16(o.y, h1, l1);
        split_bf16(o.z, h2, l2); split_bf16(o.w, h3, l3);
        ohi[4 * i + 0] = h0; ohi[4 * i + 1] = h1; ohi[4 * i + 2] = h2; ohi[4 * i + 3] = h3;
        olo[4 * i + 0] = l0; olo[4 * i + 1] = l1; olo[4 * i + 2] = l2; olo[4 * i + 3] = l3;
    }
}

// ---------------- 3-term split HMMA GEMM ----------------
// C[M,1024] = (Ahi+Alo)[M,1024] @ (Whi+Wlo)^T + bias (+res), dropping Alo@Wlo.
// CTA 128x128, BK=32, 256 threads (8 warps, warp tile 32x64), double-buffered cp.async.
#define BKD 32
#define SSTR 40
#define TILE_E (128 * SSTR)
__global__ __launch_bounds__(256) void gemm_split(
    const __nv_bfloat16* __restrict__ Ahi, const __nv_bfloat16* __restrict__ Alo,
    const __nv_bfloat16* __restrict__ Bhi, const __nv_bfloat16* __restrict__ Blo,
    const float* __restrict__ bias, const float* __restrict__ res,
    float* __restrict__ C, __nv_bfloat16* __restrict__ Chi, __nv_bfloat16* __restrict__ Clo) {
    extern __shared__ __nv_bfloat16 smem[];
    // layout: AHI[2] ALO[2] BHI[2] BLO[2], each TILE_E elts
    __nv_bfloat16* sAhi[2] = {smem + 0 * TILE_E, smem + 1 * TILE_E};
    __nv_bfloat16* sAlo[2] = {smem + 2 * TILE_E, smem + 3 * TILE_E};
    __nv_bfloat16* sBhi[2] = {smem + 4 * TILE_E, smem + 5 * TILE_E};
    __nv_bfloat16* sBlo[2] = {smem + 6 * TILE_E, smem + 7 * TILE_E};

    int tid = threadIdx.x, wid = tid >> 5, lane = tid & 31;
    int bn = blockIdx.x, bm = blockIdx.y;
    int wm = (wid >> 1) * 32;   // 4 warps along M
    int wn = (wid & 1) * 64;    // 2 warps along N

    float acc[2][8][4];
#pragma unroll
    for (int i = 0; i < 2; i++)
#pragma unroll
        for (int j = 0; j < 8; j++)
#pragma unroll
            for (int k = 0; k < 4; k++) acc[i][j][k] = 0.f;

    int lrow = tid >> 1;                 // 0..127
    int lc0 = (tid & 1) * 2;             // 16B-chunk pair {0,1} or {2,3}
    const __nv_bfloat16* gAhi = Ahi + (size_t)(bm * 128 + lrow) * DMODEL;
    const __nv_bfloat16* gAlo = Alo + (size_t)(bm * 128 + lrow) * DMODEL;
    const __nv_bfloat16* gBhi = Bhi + (size_t)(bn * 128 + lrow) * DMODEL;
    const __nv_bfloat16* gBlo = Blo + (size_t)(bn * 128 + lrow) * DMODEL;
    uint32_t rowoff = lrow * SSTR * 2;   // byte offset of this thread's row
    uint32_t dAhi[2], dAlo[2], dBhi[2], dBlo[2];
#pragma unroll
    for (int b = 0; b < 2; b++) {
        dAhi[b] = smem_u32(sAhi[b]) + rowoff;
        dAlo[b] = smem_u32(sAlo[b]) + rowoff;
        dBhi[b] = smem_u32(sBhi[b]) + rowoff;
        dBlo[b] = smem_u32(sBlo[b]) + rowoff;
    }

#define LOAD_TILE(buf, k0) do { \
    cp_async16(dAhi[buf] + (lc0 + 0) * 16, gAhi + (k0) + (lc0 + 0) * 8); \
    cp_async16(dAhi[buf] + (lc0 + 1) * 16, gAhi + (k0) + (lc0 + 1) * 8); \
    cp_async16(dAlo[buf] + (lc0 + 0) * 16, gAlo + (k0) + (lc0 + 0) * 8); \
    cp_async16(dAlo[buf] + (lc0 + 1) * 16, gAlo + (k0) + (lc0 + 1) * 8); \
    cp_async16(dBhi[buf] + (lc0 + 0) * 16, gBhi + (k0) + (lc0 + 0) * 8); \
    cp_async16(dBhi[buf] + (lc0 + 1) * 16, gBhi + (k0) + (lc0 + 1) * 8); \
    cp_async16(dBlo[buf] + (lc0 + 0) * 16, gBlo + (k0) + (lc0 + 0) * 8); \
    cp_async16(dBlo[buf] + (lc0 + 1) * 16, gBlo + (k0) + (lc0 + 1) * 8); \
    asm volatile("cp.async.commit_group;"); \
} while (0)

    LOAD_TILE(0, 0);
    LOAD_TILE(1, BKD);

    int g = lane >> 3, r = lane & 7;
    int rofs = (g & 1) * 8 + r;          // row-within-16 for ldmatrix groups
    int kofs = (g >> 1) * 8;             // k-offset for ldmatrix groups

    const int NIT = DMODEL / BKD;        // 32
    for (int it = 0; it < NIT; it++) {
        int buf = it & 1;
        if (it + 2 < NIT)
            asm volatile("cp.async.wait_group 1;" ::: "memory");
        else
            asm volatile("cp.async.wait_group 0;" ::: "memory");
        __syncthreads();

#pragma unroll
        for (int kk = 0; kk < 2; kk++) {
            int kb = kk * 16 + kofs;
            uint32_t aH[2][4];
#pragma unroll
            for (int mt = 0; mt < 2; mt++)
                ldsm_x4(aH[mt][0], aH[mt][1], aH[mt][2], aH[mt][3],
                        smem_u32(sAhi[buf] + (wm + mt * 16 + rofs) * SSTR + kb));
            uint32_t bF[8][2];
#pragma unroll
            for (int np = 0; np < 4; np++) {
                uint32_t r0, r1, r2, r3;
                ldsm_x4(r0, r1, r2, r3,
                        smem_u32(sBhi[buf] + (wn + np * 16 + rofs) * SSTR + kb));
                bF[np * 2 + 0][0] = r0; bF[np * 2 + 0][1] = r2;
                bF[np * 2 + 1][0] = r1; bF[np * 2 + 1][1] = r3;
            }
            // term 1: Ahi @ Whi
#pragma unroll
            for (int mt = 0; mt < 2; mt++)
#pragma unroll
                for (int nt = 0; nt < 8; nt++)
                    mma_bf16(acc[mt][nt][0], acc[mt][nt][1], acc[mt][nt][2], acc[mt][nt][3],
                             aH[mt][0], aH[mt][1], aH[mt][2], aH[mt][3],
                             bF[nt][0], bF[nt][1]);
            // term 2: Alo @ Whi (reuse bF)
            {
                uint32_t aL[2][4];
#pragma unroll
                for (int mt = 0; mt < 2; mt++)
                    ldsm_x4(aL[mt][0], aL[mt][1], aL[mt][2], aL[mt][3],
                            smem_u32(sAlo[buf] + (wm + mt * 16 + rofs) * SSTR + kb));
#pragma unroll
                for (int mt = 0; mt < 2; mt++)
#pragma unroll
                    for (int nt = 0; nt < 8; nt++)
                        mma_bf16(acc[mt][nt][0], acc[mt][nt][1], acc[mt][nt][2], acc[mt][nt][3],
                                 aL[mt][0], aL[mt][1], aL[mt][2], aL[mt][3],
                                 bF[nt][0], bF[nt][1]);
            }
            // term 3: Ahi @ Wlo (overwrite bF with Wlo frags)
#pragma unroll
            for (int np = 0; np < 4; np++) {
                uint32_t r0, r1, r2, r3;
                ldsm_x4(r0, r1, r2, r3,
                        smem_u32(sBlo[buf] + (wn + np * 16 + rofs) * SSTR + kb));
                bF[np * 2 + 0][0] = r0; bF[np * 2 + 0][1] = r2;
                bF[np * 2 + 1][0] = r1; bF[np * 2 + 1][1] = r3;
            }
#pragma unroll
            for (int mt = 0; mt < 2; mt++)
#pragma unroll
                for (int nt = 0; nt < 8; nt++)
                    mma_bf16(acc[mt][nt][0], acc[mt][nt][1], acc[mt][nt][2], acc[mt][nt][3],
                             aH[mt][0], aH[mt][1], aH[mt][2], aH[mt][3],
                             bF[nt][0], bF[nt][1]);
        }
        __syncthreads();
        if (it + 2 < NIT) LOAD_TILE(buf, (it + 2) * BKD);
    }
#undef LOAD_TILE

    // epilogue
    int gid = lane >> 2, tig = lane & 3;
#pragma unroll
    for (int mt = 0; mt < 2; mt++) {
#pragma unroll
        for (int half = 0; half < 2; half++) {
            int m = bm * 128 + wm + mt * 16 + gid + half * 8;
            float* crow = C + (size_t)m * DMODEL;
            const float* rrow = res ? res + (size_t)m * DMODEL : nullptr;
            __nv_bfloat16* hrow = Chi ? Chi + (size_t)m * DMODEL : nullptr;
            __nv_bfloat16* lrow2 = Clo ? Clo + (size_t)m * DMODEL : nullptr;
#pragma unroll
            for (int nt = 0; nt < 8; nt++) {
                int ncol = bn * 128 + wn + nt * 8 + tig * 2;
                float v0 = acc[mt][nt][half * 2 + 0] + bias[ncol];
                float v1 = acc[mt][nt][half * 2 + 1] + bias[ncol + 1];
                if (rrow) { v0 += rrow[ncol]; v1 += rrow[ncol + 1]; }
                *(float2*)(crow + ncol) = make_float2(v0, v1);
                if (hrow) {
                    __nv_bfloat16 h0, l0, h1, l1;
                    split_bf16(v0, h0, l0);
                    split_bf16(v1, h1, l1);
                    hrow[ncol] = h0; hrow[ncol + 1] = h1;
                    lrow2[ncol] = l0; lrow2[ncol + 1] = l1;
                }
            }
        }
    }
}

// ---------------- flash attention (fp32 compute, bf16 hi/lo output) ----------------
template <int DH>
__global__ __launch_bounds__(256) void attn_kernel(
    const float* __restrict__ Q, const float* __restrict__ Kt,
    const float* __restrict__ Vt, const void* __restrict__ xids,
    __nv_bfloat16* __restrict__ Ohi, __nv_bfloat16* __restrict__ Olo) {
    extern __shared__ float smf[];
    const int STR = DH + 4;
    const int CH = DH / 4;
    float* Qs = smf;
    float* Ks = Qs + 64 * STR;
    float* Vs = Ks + 64 * STR;
    float* Ss = Vs + 64 * STR;   // [64][65]
    __shared__ int msk[64];

    int qt = blockIdx.x, h = blockIdx.y, b = blockIdx.z;
    int tid = threadIdx.x;
    float scale = rsqrtf((float)DH);
    int q0 = qt * 64;
    const int vecs = 64 * (DH / 4);

    for (int i = tid; i < vecs; i += 256) {
        int rr = i / (DH / 4), cc2 = i % (DH / 4);
        float4 v = *(const float4*)(Q + ((size_t)(b * SEQ + q0 + rr) * DMODEL + h * DH + cc2 * 4));
        *(float4*)&Qs[rr * STR + cc2 * 4] = v;
    }

    int qr = tid & 63;
    int cc = tid >> 6;
    float acc[CH];
#pragma unroll
    for (int i = 0; i < CH; i++) acc[i] = 0.f;
    float m_i = -1e30f, l_i = 0.f;

    int sq = tid >> 2;
    int skc = tid & 3;
    int is64 = g_is64;

    for (int kt = 0; kt < SEQ / 64; kt++) {
        int k0 = kt * 64;
        __syncthreads();
        for (int i = tid; i < vecs; i += 256) {
            int rr = i / (DH / 4), cc2 = i % (DH / 4);
            size_t base = ((size_t)(b * SEQ + k0 + rr) * DMODEL + h * DH + cc2 * 4);
            *(float4*)&Ks[rr * STR + cc2 * 4] = *(const float4*)(Kt + base);
            *(float4*)&Vs[rr * STR + cc2 * 4] = *(const float4*)(Vt + base);
        }
        if (tid < 64) {
            long long idv = is64 ? ((const long long*)xids)[b * SEQ + k0 + tid]
                                 : (long long)((const int*)xids)[b * SEQ + k0 + tid];
            msk[tid] = (idv != 0) ? 1 : 0;
        }
        __syncthreads();

        {
            float dots[16];
#pragma unroll
            for (int j = 0; j < 16; j++) dots[j] = 0.f;
            for (int x = 0; x < DH; x += 4) {
                float4 qv = *(float4*)&Qs[sq * STR + x];
#pragma unroll
                for (int j = 0; j < 16; j++) {
                    float4 kv = *(float4*)&Ks[(skc + 4 * j) * STR + x];
                    dots[j] += qv.x * kv.x + qv.y * kv.y + qv.z * kv.z + qv.w * kv.w;
                }
            }
#pragma unroll
            for (int j = 0; j < 16; j++) {
                int kk = skc + 4 * j;
                Ss[sq * 65 + kk] = msk[kk] ? dots[j] * scale : -1e30f;
            }
        }
        __syncthreads();

        float rowmax = -1e30f;
        for (int kk = 0; kk < 64; kk++) rowmax = fmaxf(rowmax, Ss[qr * 65 + kk]);
        float newm = fmaxf(m_i, rowmax);
        float factor = __expf(m_i - newm);
        l_i *= factor;
#pragma unroll
        for (int i = 0; i < CH; i++) acc[i] *= factor;
        for (int kk = 0; kk < 64; kk++) {
            float s = Ss[qr * 65 + kk];
            float p = (s > -1e29f) ? __expf(s - newm) : 0.f;
            l_i += p;
            const float4* vr = (const float4*)&Vs[kk * STR + cc * CH];
#pragma unroll
            for (int i = 0; i < CH / 4; i++) {
                float4 v = vr[i];
                acc[4 * i + 0] += p * v.x;
                acc[4 * i + 1] += p * v.y;
                acc[4 * i + 2] += p * v.z;
                acc[4 * i + 3] += p * v.w;
            }
        }
        m_i = newm;
    }

    float inv = 1.0f / fmaxf(l_i, 1e-20f);
    size_t base = (size_t)(b * SEQ + q0 + qr) * DMODEL + h * DH + cc * CH;
#pragma unroll
    for (int i = 0; i < CH; i++) {
        float v = acc[i] * inv;
        __nv_bfloat16 hi, lo;
        split_bf16(v, hi, lo);
        Ohi[base + i] = hi;
        Olo[base + i] = lo;
    }
}

// ---------------- masked mean pooling of (g_h2 + g_emb) ----------------
__global__ void pool_kernel(const void* __restrict__ xids) {
    int b = blockIdx.y;
    int col = blockIdx.x * 128 + threadIdx.x;
    __shared__ int smask[SEQ];
    int is64 = g_is64;
    for (int s = threadIdx.x; s < SEQ; s += 128) {
        long long idv = is64 ? ((const long long*)xids)[b * SEQ + s]
                             : (long long)((const int*)xids)[b * SEQ + s];
        smask[s] = (idv != 0) ? 1 : 0;
    }
    __syncthreads();
    float acc = 0.f;
    int cnt = 0;
    for (int s = 0; s < SEQ; s++) {
        if (smask[s]) {
            size_t idx = (size_t)(b * SEQ + s) * DMODEL + col;
            acc += g_h2[idx] + g_emb[idx];
            cnt++;
        }
    }
    g_pooled[b * DMODEL + col] = acc / (float)cnt;
}

// ---------------- LayerNorm + linear head ----------------
__global__ void lnlin_kernel(const float* __restrict__ ng, const float* __restrict__ nb,
                             const float* __restrict__ lw, const float* __restrict__ lb,
                             float* __restrict__ out) {
    int b = blockIdx.x, tid = threadIdx.x;
    __shared__ float red[256];
    float x[4];
    float s = 0.f;
#pragma unroll
    for (int k = 0; k < 4; k++) {
        x[k] = g_pooled[b * DMODEL + tid + k * 256];
        s += x[k];
    }
    red[tid] = s; __syncthreads();
    for (int st = 128; st > 0; st >>= 1) { if (tid < st) red[tid] += red[tid + st]; __syncthreads(); }
    float mu = red[0] / (float)DMODEL;
    __syncthreads();
    float s2 = 0.f;
#pragma unroll
    for (int k = 0; k < 4; k++) { float d = x[k] - mu; s2 += d * d; }
    red[tid] = s2; __syncthreads();
    for (int st = 128; st > 0; st >>= 1) { if (tid < st) red[tid] += red[tid + st]; __syncthreads(); }
    float var = red[0] / (float)DMODEL;
    float rstd = rsqrtf(var + 1e-5f);
    __syncthreads();
    float acc = 0.f;
#pragma unroll
    for (int k = 0; k < 4; k++) {
        int col = tid + k * 256;
        acc += ((x[k] - mu) * rstd * ng[col] + nb[col]) * lw[col];
    }
    red[tid] = acc; __syncthreads();
    for (int st = 128; st > 0; st >>= 1) { if (tid < st) red[tid] += red[tid + st]; __syncthreads(); }
    if (tid == 0) out[b] = red[0] + lb[0];
}

// ---------------- launch ----------------
extern "C" void kernel_launch(void* const* d_in, const int* in_sizes, int n_in,
                              void* d_out, int out_size) {
    const void*  x      = d_in[0];
    const float* emb_w  = (const float*)d_in[1];
    const float* pos_w  = (const float*)d_in[2];
    const float* a1_qw  = (const float*)d_in[3];
    const float* a1_qb  = (const float*)d_in[4];
    const float* a1_kw  = (const float*)d_in[5];
    const float* a1_kb  = (const float*)d_in[6];
    const float* a1_vw  = (const float*)d_in[7];
    const float* a1_vb  = (const float*)d_in[8];
    const float* a1_pw  = (const float*)d_in[9];
    const float* a1_pb  = (const float*)d_in[10];
    const float* a2_qw  = (const float*)d_in[11];
    const float* a2_qb  = (const float*)d_in[12];
    const float* a2_kw  = (const float*)d_in[13];
    const float* a2_kb  = (const float*)d_in[14];
    const float* a2_vw  = (const float*)d_in[15];
    const float* a2_vb  = (const float*)d_in[16];
    const float* a2_pw  = (const float*)d_in[17];
    const float* a2_pb  = (const float*)d_in[18];
    const float* norm_g = (const float*)d_in[19];
    const float* norm_b = (const float*)d_in[20];
    const float* lin_w  = (const float*)d_in[21];
    const float* lin_b  = (const float*)d_in[22];
    float* out = (float*)d_out;

    float *p_emb, *p_h1, *p_h2, *p_q, *p_k, *p_v;
    __nv_bfloat16 *p_ahi, *p_alo, *p_bhi, *p_blo, *p_whi, *p_wlo;
    cudaGetSymbolAddress((void**)&p_emb, g_emb);
    cudaGetSymbolAddress((void**)&p_h1,  g_h1);
    cudaGetSymbolAddress((void**)&p_h2,  g_h2);
    cudaGetSymbolAddress((void**)&p_q,   g_q);
    cudaGetSymbolAddress((void**)&p_k,   g_k);
    cudaGetSymbolAddress((void**)&p_v,   g_v);
    cudaGetSymbolAddress((void**)&p_ahi, g_ahi);
    cudaGetSymbolAddress((void**)&p_alo, g_alo);
    cudaGetSymbolAddress((void**)&p_bhi, g_bhi);
    cudaGetSymbolAddress((void**)&p_blo, g_blo);
    cudaGetSymbolAddress((void**)&p_whi, g_whi);
    cudaGetSymbolAddress((void**)&p_wlo, g_wlo);

    const size_t WSZ = (size_t)DMODEL * DMODEL;
    const int GEMM_SMEM = 8 * TILE_E * 2;   // 81920 bytes
    cudaFuncSetAttribute(gemm_split, cudaFuncAttributeMaxDynamicSharedMemorySize, GEMM_SMEM);
    const int smem128 = (3 * 64 * (128 + 4) + 64 * 65) * 4;
    const int smem256 = (3 * 64 * (256 + 4) + 64 * 65) * 4;
    cudaFuncSetAttribute(attn_kernel<128>, cudaFuncAttributeMaxDynamicSharedMemorySize, smem128);
    cudaFuncSetAttribute(attn_kernel<256>, cudaFuncAttributeMaxDynamicSharedMemorySize, smem256);

    detect_kernel<<<1, 256>>>((const int*)x);

    // Transpose + hi/lo split the 8 weights
    dim3 tg(32, 32), tb(32, 8);
    wtrans_kernel<<<tg, tb>>>(a1_qw, p_whi + 0 * WSZ, p_wlo + 0 * WSZ);
    wtrans_kernel<<<tg, tb>>>(a1_kw, p_whi + 1 * WSZ, p_wlo + 1 * WSZ);
    wtrans_kernel<<<tg, tb>>>(a1_vw, p_whi + 2 * WSZ, p_wlo + 2 * WSZ);
    wtrans_kernel<<<tg, tb>>>(a1_pw, p_whi + 3 * WSZ, p_wlo + 3 * WSZ);
    wtrans_kernel<<<tg, tb>>>(a2_qw, p_whi + 4 * WSZ, p_wlo + 4 * WSZ);
    wtrans_kernel<<<tg, tb>>>(a2_kw, p_whi + 5 * WSZ, p_wlo + 5 * WSZ);
    wtrans_kernel<<<tg, tb>>>(a2_vw, p_whi + 6 * WSZ, p_wlo + 6 * WSZ);
    wtrans_kernel<<<tg, tb>>>(a2_pw, p_whi + 7 * WSZ, p_wlo + 7 * WSZ);

    embed_kernel<<<NTOK, 256>>>(x, emb_w, pos_w);   // writes g_emb + g_ahi/g_alo

    dim3 gg(DMODEL / 128, NTOK / 128);   // (8, 256)

    // Layer 1 (8 heads, dh=128); A = emb (g_ahi/g_alo)
    gemm_split<<<gg, 256, GEMM_SMEM>>>(p_ahi, p_alo, p_whi + 0 * WSZ, p_wlo + 0 * WSZ,
                                       a1_qb, nullptr, p_q, nullptr, nullptr);
    gemm_split<<<gg, 256, GEMM_SMEM>>>(p_ahi, p_alo, p_whi + 1 * WSZ, p_wlo + 1 * WSZ,
                                       a1_kb, nullptr, p_k, nullptr, nullptr);
    gemm_split<<<gg, 256, GEMM_SMEM>>>(p_ahi, p_alo, p_whi + 2 * WSZ, p_wlo + 2 * WSZ,
                                       a1_vb, nullptr, p_v, nullptr, nullptr);
    // attention writes g_bhi/g_blo
    attn_kernel<128><<<dim3(SEQ / 64, 8, BATCH), 256, smem128>>>(p_q, p_k, p_v, x, p_bhi, p_blo);
    // proj layer1: h1 fp32 + hi/lo into g_ahi/g_alo (emb hi/lo no longer needed)
    gemm_split<<<gg, 256, GEMM_SMEM>>>(p_bhi, p_blo, p_whi + 3 * WSZ, p_wlo + 3 * WSZ,
                                       a1_pb, p_emb, p_h1, p_ahi, p_alo);

    // Layer 2 (4 heads, dh=256); A = h1 (g_ahi/g_alo)
    gemm_split<<<gg, 256, GEMM_SMEM>>>(p_ahi, p_alo, p_whi + 4 * WSZ, p_wlo + 4 * WSZ,
                                       a2_qb, nullptr, p_q, nullptr, nullptr);
    gemm_split<<<gg, 256, GEMM_SMEM>>>(p_ahi, p_alo, p_whi + 5 * WSZ, p_wlo + 5 * WSZ,
                                       a2_kb, nullptr, p_k, nullptr, nullptr);
    gemm_split<<<gg, 256, GEMM_SMEM>>>(p_ahi, p_alo, p_whi + 6 * WSZ, p_wlo + 6 * WSZ,
                                       a2_vb, nullptr, p_v, nullptr, nullptr);
    attn_kernel<256><<<dim3(SEQ / 64, 4, BATCH), 256, smem256>>>(p_q, p_k, p_v, x, p_bhi, p_blo);
    gemm_split<<<gg, 256, GEMM_SMEM>>>(p_bhi, p_blo, p_whi + 7 * WSZ, p_wlo + 7 * WSZ,
                                       a2_pb, p_h1, p_h2, nullptr, nullptr);

    // Pool + LN + head
    pool_kernel<<<dim3(DMODEL / 128, BATCH), 128>>>(x);
    lnlin_kernel<<<BATCH, 256>>>(norm_g, norm_b, lin_w, lin_b, out);
}